// round 7
// baseline (speedup 1.0000x reference)
#include <cuda_runtime.h>
#include <cuda_fp16.h>
#include <cuda_fp8.h>
#include <cstdint>
#include <math.h>

#define BATCH 4
#define CH    512
#define HW    4096
#define NGRP  32
#define CPG   16

static const size_t CHW = (size_t)CH * HW;
static const size_t SHW = (size_t)HW * HW;
#define CC (CH * CH)

// ---------------- scratch ----------------
__device__ __half   g_xn [BATCH * CH * HW];   // [c, hw] f16
__device__ __half   g_xnT[BATCH * CH * HW];   // [hw, c] f16
__device__ uint8_t  g_q  [BATCH * CH * HW];   // [hw, c] fp8
__device__ uint8_t  g_k  [BATCH * CH * HW];   // [hw, c] fp8
__device__ uint8_t  g_v  [BATCH * CH * HW];   // [c, hw] fp8
__device__ __half   g_s  [BATCH * HW * HW];   // f16 scores (128 MB)
__device__ uint8_t  g_at [BATCH * HW * HW];   // fp8 attn*256 (64 MB)
__device__ __half   g_o2 [BATCH * CH * HW];   // [hw, c] f16
__device__ __half   g_w  [4 * CH * CH];       // wq, wk, wv, wp f16

// ---------------- PTX helpers (family-portable) ----------------
__device__ __forceinline__ uint32_t smem_u32(const void* p) {
    uint32_t a;
    asm("{ .reg .u64 t; cvta.to.shared.u64 t, %1; cvt.u32.u64 %0, t; }"
        : "=r"(a) : "l"(p));
    return a;
}
__device__ __forceinline__ void cp16(uint32_t s, const void* g) {
    asm volatile("cp.async.cg.shared.global [%0], [%1], 16;"
                 :: "r"(s), "l"(__cvta_generic_to_global(g)) : "memory");
}
#define CP_COMMIT() asm volatile("cp.async.commit_group;" ::: "memory")
#define CP_WAIT1()  asm volatile("cp.async.wait_group 1;"  ::: "memory")

__device__ __forceinline__ void ldsm_x4(uint32_t* r, uint32_t addr) {
    asm volatile("ldmatrix.sync.aligned.m8n8.x4.shared.b16 {%0,%1,%2,%3}, [%4];"
        : "=r"(r[0]), "=r"(r[1]), "=r"(r[2]), "=r"(r[3]) : "r"(addr));
}
// f16 inputs, f16 accumulator (packed pairs)
__device__ __forceinline__ void mma_h(uint32_t* c, const uint32_t* a,
                                      uint32_t b0, uint32_t b1) {
    asm volatile(
        "mma.sync.aligned.m16n8k16.row.col.f16.f16.f16.f16 "
        "{%0,%1}, {%2,%3,%4,%5}, {%6,%7}, {%0,%1};"
        : "+r"(c[0]), "+r"(c[1])
        : "r"(a[0]), "r"(a[1]), "r"(a[2]), "r"(a[3]), "r"(b0), "r"(b1));
}
// fp8 e4m3 inputs, f16 accumulator
__device__ __forceinline__ void mma_f8h(uint32_t* c, const uint32_t* a,
                                        uint32_t b0, uint32_t b1) {
    asm volatile(
        "mma.sync.aligned.m16n8k32.row.col.f16.e4m3.e4m3.f16 "
        "{%0,%1}, {%2,%3,%4,%5}, {%6,%7}, {%0,%1};"
        : "+r"(c[0]), "+r"(c[1])
        : "r"(a[0]), "r"(a[1]), "r"(a[2]), "r"(a[3]), "r"(b0), "r"(b1));
}
__device__ __forceinline__ uint16_t f2_to_e4m3x2(float x0, float x1) {
    return (uint16_t)__nv_cvt_float2_to_fp8x2(make_float2(x0, x1),
                                              __NV_SATFINITE, __NV_E4M3);
}

// ---------------------------------------------------------------------------
// GroupNorm -> f16 [c, hw]
// ---------------------------------------------------------------------------
__global__ __launch_bounds__(256) void groupnorm_kernel(
    const float* __restrict__ x, const float* __restrict__ scale,
    const float* __restrict__ bias, __half* __restrict__ xn)
{
    const int b = blockIdx.x / NGRP, g = blockIdx.x % NGRP;
    const size_t base = ((size_t)b * CH + (size_t)g * CPG) * HW;
    const int n4 = CPG * HW / 4;

    const float4* xin = reinterpret_cast<const float4*>(x + base);
    float s = 0.f, ss = 0.f;
    for (int i = threadIdx.x; i < n4; i += 256) {
        float4 t = xin[i];
        s  += t.x + t.y + t.z + t.w;
        ss += t.x * t.x + t.y * t.y + t.z * t.z + t.w * t.w;
    }
    __shared__ float r1[256], r2[256];
    r1[threadIdx.x] = s; r2[threadIdx.x] = ss;
    __syncthreads();
    for (int off = 128; off > 0; off >>= 1) {
        if (threadIdx.x < off) {
            r1[threadIdx.x] += r1[threadIdx.x + off];
            r2[threadIdx.x] += r2[threadIdx.x + off];
        }
        __syncthreads();
    }
    const float inv_n = 1.f / (float)(CPG * HW);
    const float mean = r1[0] * inv_n;
    const float var  = fmaxf(r2[0] * inv_n - mean * mean, 0.f);
    const float rstd = rsqrtf(var + 1e-6f);

    uint2* xo = reinterpret_cast<uint2*>(xn + base);
    for (int i = threadIdx.x; i < n4; i += 256) {
        const int c = g * CPG + (i >> 10);
        const float a = scale[c] * rstd;
        const float d = bias[c] - mean * a;
        float4 t = xin[i];
        __half2 h0 = __floats2half2_rn(t.x * a + d, t.y * a + d);
        __half2 h1 = __floats2half2_rn(t.z * a + d, t.w * a + d);
        uint2 o;
        o.x = *reinterpret_cast<uint32_t*>(&h0);
        o.y = *reinterpret_cast<uint32_t*>(&h1);
        xo[i] = o;
    }
}

// ---------------------------------------------------------------------------
// 16-bit transpose [R, C] -> [C, R]
// ---------------------------------------------------------------------------
__global__ __launch_bounds__(256) void transpose_h16(
    const uint16_t* __restrict__ in, uint16_t* __restrict__ out, int R, int C)
{
    __shared__ uint16_t tile[64][72];
    const size_t zoff = (size_t)blockIdx.z * (size_t)R * C;
    const int r0 = blockIdx.y * 64, c0 = blockIdx.x * 64;

    #pragma unroll
    for (int it = 0; it < 2; it++) {
        int idx = threadIdx.x + it * 256;
        int r = idx >> 3, c8 = idx & 7;
        uint4 v = *reinterpret_cast<const uint4*>(in + zoff + (size_t)(r0 + r) * C + c0 + c8 * 8);
        *reinterpret_cast<uint4*>(&tile[r][c8 * 8]) = v;
    }
    __syncthreads();
    #pragma unroll
    for (int it = 0; it < 2; it++) {
        int idx = threadIdx.x + it * 256;
        int c = idx >> 3, r8 = idx & 7;
        uint16_t tmp[8];
        #pragma unroll
        for (int i = 0; i < 8; i++) tmp[i] = tile[r8 * 8 + i][c];
        *reinterpret_cast<uint4*>(out + zoff + (size_t)(c0 + c) * R + r0 + r8 * 8) =
            *reinterpret_cast<uint4*>(tmp);
    }
}

// ---------------------------------------------------------------------------
// weights fp32 -> f16
// ---------------------------------------------------------------------------
__global__ __launch_bounds__(256) void cvt_w_kernel(
    const float* __restrict__ a, const float* __restrict__ b,
    const float* __restrict__ c, const float* __restrict__ d,
    __half* __restrict__ w)
{
    const int i = blockIdx.x * 256 + threadIdx.x;
    const float* s = (blockIdx.y == 0) ? a : (blockIdx.y == 1) ? b : (blockIdx.y == 2) ? c : d;
    w[(size_t)blockIdx.y * CC + i] = __float2half(s[i]);
}

// ---------------------------------------------------------------------------
// Unified GEMM, f16 accumulate: D[M,N] = alpha*A[M,K]@B[N,K]^T + bias + addc
// IT: 0 = f16 inputs (k16), 1 = fp8 e4m3 inputs (k32)
// OT: 0 = fp32 out, 1 = f16 out, 2 = fp8 out
// 128x128 tile, 8 warps (4Mx2N, warp 32x64), 64B smem rows, 3-stage cp.async.
// ---------------------------------------------------------------------------
#define PITCH  80
#define OPSZ   10240           // 128 * 80
#define STG_SZ 20480
#define SMEM_G 61440           // 3 * STG_SZ

template<int IT, int OT>
__global__ void __launch_bounds__(256, 3) gemm_u(
    const void* __restrict__ Ag, const void* __restrict__ Bg,
    void* __restrict__ Cout,
    const float* __restrict__ bias_m, const float* __restrict__ bias_n,
    int M, int N, int K, float alpha, float addc,
    size_t sA, size_t sB, size_t sC)
{
    constexpr int ES = (IT == 0) ? 2 : 1;     // bytes/elem
    // chunk = 64 bytes of K per row: 32 f16 or 64 fp8 elems
    extern __shared__ __align__(16) char smem[];
    const uint32_t sb = smem_u32(smem);

    const int tid  = threadIdx.x;
    const int lane = tid & 31;
    const int wid  = tid >> 5;
    const int wm   = wid >> 1;          // 0..3
    const int wn   = wid & 1;           // 0..1
    const int bm = blockIdx.y * 128;
    const int bn = blockIdx.x * 128;

    const uint8_t* Ab = (const uint8_t*)Ag + ((size_t)blockIdx.z * sA + (size_t)bm * K) * ES;
    const uint8_t* Bb = (const uint8_t*)Bg + ((size_t)blockIdx.z * sB + (size_t)bn * K) * ES;

    // cp.async: 2 slots/thread/operand (128 rows x 4 chunks / 256 thr)
    uint32_t so[2];
    size_t   gb[2];
    #pragma unroll
    for (int j = 0; j < 2; j++) {
        const int idx = tid + j * 256;
        const int row = idx >> 2, cc = idx & 3;
        so[j] = (uint32_t)row * PITCH + cc * 16;
        gb[j] = (size_t)row * K * ES + cc * 16;
    }

    const int nk = K * ES >> 6;     // chunks of 64 K-bytes

    #pragma unroll
    for (int s = 0; s < 2; s++) {
        const uint32_t kb = (uint32_t)s * 64;
        const uint32_t st = sb + s * STG_SZ;
        #pragma unroll
        for (int j = 0; j < 2; j++) {
            cp16(st + so[j],        Ab + gb[j] + kb);
            cp16(st + OPSZ + so[j], Bb + gb[j] + kb);
        }
        CP_COMMIT();
    }

    uint32_t acc[2][8][2];
    #pragma unroll
    for (int i = 0; i < 2; i++)
        #pragma unroll
        for (int j = 0; j < 8; j++) { acc[i][j][0] = 0u; acc[i][j][1] = 0u; }

    const uint32_t lrow = lane & 15;
    const uint32_t lsel = (lane >> 4) * 16;

    int buf = 0;
    for (int ck = 0; ck < nk; ck++) {
        CP_WAIT1();
        __syncthreads();

        if (ck + 2 < nk) {
            const uint32_t kb = (uint32_t)(ck + 2) * 64;
            const uint32_t st = sb + ((buf + 2) % 3) * STG_SZ;
            #pragma unroll
            for (int j = 0; j < 2; j++) {
                cp16(st + so[j],        Ab + gb[j] + kb);
                cp16(st + OPSZ + so[j], Bb + gb[j] + kb);
            }
        }
        CP_COMMIT();

        const uint32_t sa  = sb + buf * STG_SZ;
        const uint32_t sbm = sa + OPSZ;
        #pragma unroll
        for (int kf = 0; kf < 2; kf++) {
            const uint32_t kofs = kf * 32 + lsel;
            uint32_t ar[2][4];
            #pragma unroll
            for (int mi = 0; mi < 2; mi++)
                ldsm_x4(ar[mi], sa + (wm * 32 + mi * 16 + lrow) * PITCH + kofs);
            uint32_t br[4][4];
            #pragma unroll
            for (int nb = 0; nb < 4; nb++)
                ldsm_x4(br[nb], sbm + (wn * 64 + nb * 16 + lrow) * PITCH + kofs);
            #pragma unroll
            for (int mi = 0; mi < 2; mi++)
                #pragma unroll
                for (int nj = 0; nj < 8; nj++) {
                    const int nb = nj >> 1, od = nj & 1;
                    if (IT == 0)
                        mma_h(acc[mi][nj], ar[mi], br[nb][od], br[nb][od + 2]);
                    else
                        mma_f8h(acc[mi][nj], ar[mi], br[nb][od], br[nb][od + 2]);
                }
        }
        buf = (buf + 1) % 3;
        // no trailing barrier: writes at iter ck target buffer (ck+2)%3,
        // whose readers finished before this iteration's leading barrier.
    }

    // ---- epilogue ----
    const int gid = lane >> 2, tig = lane & 3;
    #pragma unroll
    for (int mi = 0; mi < 2; mi++) {
        #pragma unroll
        for (int r2 = 0; r2 < 2; r2++) {
            const int m = bm + wm * 32 + mi * 16 + gid + r2 * 8;
            const float bmv = (bias_m ? bias_m[m] : 0.f) + addc;
            #pragma unroll
            for (int nj = 0; nj < 8; nj++) {
                const int n = bn + wn * 64 + nj * 8 + tig * 2;
                const __half2 h = *reinterpret_cast<const __half2*>(&acc[mi][nj][r2]);
                const float2 f = __half22float2(h);
                float x0 = f.x * alpha + bmv;
                float x1 = f.y * alpha + bmv;
                if (bias_n) { x0 += bias_n[n]; x1 += bias_n[n + 1]; }
                const size_t off = (size_t)blockIdx.z * sC + (size_t)m * N + n;
                if (OT == 0) {
                    *reinterpret_cast<float2*>((float*)Cout + off) = make_float2(x0, x1);
                } else if (OT == 1) {
                    __half2 oh = __floats2half2_rn(x0, x1);
                    *reinterpret_cast<uint32_t*>((__half*)Cout + off)
                        = *reinterpret_cast<uint32_t*>(&oh);
                } else {
                    *reinterpret_cast<uint16_t*>((uint8_t*)Cout + off)
                        = f2_to_e4m3x2(x0, x1);
                }
            }
        }
    }
}

// ---------------------------------------------------------------------------
// Row softmax: f16 in -> fp8 out scaled by 256. One block per 4096-row.
// ---------------------------------------------------------------------------
__global__ __launch_bounds__(256) void softmax_kernel(
    const __half* __restrict__ s, uint8_t* __restrict__ at)
{
    const uint4* r4 = reinterpret_cast<const uint4*>(s + (size_t)blockIdx.x * HW);
    uint4* o4 = reinterpret_cast<uint4*>(at + (size_t)blockIdx.x * HW);

    float v[16];
    #pragma unroll
    for (int i = 0; i < 2; i++) {
        uint4 t = r4[threadIdx.x * 2 + i];
        const uint32_t* u = reinterpret_cast<const uint32_t*>(&t);
        #pragma unroll
        for (int j = 0; j < 4; j++) {
            float2 f = __half22float2(*reinterpret_cast<const __half2*>(&u[j]));
            v[i * 8 + j * 2]     = f.x;
            v[i * 8 + j * 2 + 1] = f.y;
        }
    }
    float mx = -1e30f;
    #pragma unroll
    for (int i = 0; i < 16; i++) mx = fmaxf(mx, v[i]);

    __shared__ float red[256];
    red[threadIdx.x] = mx;
    __syncthreads();
    for (int off = 128; off > 0; off >>= 1) {
        if (threadIdx.x < off)
            red[threadIdx.x] = fmaxf(red[threadIdx.x], red[threadIdx.x + off]);
        __syncthreads();
    }
    mx = red[0];
    __syncthreads();

    float sum = 0.f;
    #pragma unroll
    for (int i = 0; i < 16; i++) { v[i] = __expf(v[i] - mx); sum += v[i]; }
    red[threadIdx.x] = sum;
    __syncthreads();
    for (int off = 128; off > 0; off >>= 1) {
        if (threadIdx.x < off) red[threadIdx.x] += red[threadIdx.x + off];
        __syncthreads();
    }
    const float inv = 256.f / red[0];

    uint4 t;
    uint32_t* u = reinterpret_cast<uint32_t*>(&t);
    #pragma unroll
    for (int j = 0; j < 4; j++) {
        uint32_t lo = f2_to_e4m3x2(v[j * 4 + 0] * inv, v[j * 4 + 1] * inv);
        uint32_t hi = f2_to_e4m3x2(v[j * 4 + 2] * inv, v[j * 4 + 3] * inv);
        u[j] = lo | (hi << 16);
    }
    o4[threadIdx.x] = t;
}

// ---------------------------------------------------------------------------
// Launch
// ---------------------------------------------------------------------------
extern "C" void kernel_launch(void* const* d_in, const int* in_sizes, int n_in,
                              void* d_out, int out_size)
{
    const float* x  = (const float*)d_in[0];
    const float* gs = (const float*)d_in[1];
    const float* gb = (const float*)d_in[2];
    const float* wq = (const float*)d_in[3];
    const float* bq = (const float*)d_in[4];
    const float* wk = (const float*)d_in[5];
    const float* bk = (const float*)d_in[6];
    const float* wv = (const float*)d_in[7];
    const float* bv = (const float*)d_in[8];
    const float* wp = (const float*)d_in[9];
    const float* bp = (const float*)d_in[10];
    float* out = (float*)d_out;

    __half *xn, *xnT, *s, *o2, *w;
    uint8_t *q, *k, *v, *at;
    cudaGetSymbolAddress((void**)&xn,  g_xn);
    cudaGetSymbolAddress((void**)&xnT, g_xnT);
    cudaGetSymbolAddress((void**)&q,   g_q);
    cudaGetSymbolAddress((void**)&k,   g_k);
    cudaGetSymbolAddress((void**)&v,   g_v);
    cudaGetSymbolAddress((void**)&s,   g_s);
    cudaGetSymbolAddress((void**)&at,  g_at);
    cudaGetSymbolAddress((void**)&o2,  g_o2);
    cudaGetSymbolAddress((void**)&w,   g_w);

    cudaFuncSetAttribute(gemm_u<0, 2>, cudaFuncAttributeMaxDynamicSharedMemorySize, SMEM_G);
    cudaFuncSetAttribute(gemm_u<0, 0>, cudaFuncAttributeMaxDynamicSharedMemorySize, SMEM_G);
    cudaFuncSetAttribute(gemm_u<1, 1>, cudaFuncAttributeMaxDynamicSharedMemorySize, SMEM_G);
    cudaFuncSetAttribute(gemm_u<1, 2>, cudaFuncAttributeMaxDynamicSharedMemorySize, SMEM_G);

    // 0) weights -> f16
    cvt_w_kernel<<<dim3(CC / 256, 4), 256>>>(wq, wk, wv, wp, w);

    // 1) GroupNorm -> f16 [c, hw]
    groupnorm_kernel<<<BATCH * NGRP, 256>>>(x, gs, gb, xn);

    // 2) transpose xn -> xnT [hw, c]
    transpose_h16<<<dim3(HW / 64, CH / 64, BATCH), 256>>>(
        (const uint16_t*)xn, (uint16_t*)xnT, CH, HW);

    // 3) Q, K -> fp8 [hw, c]  (bias over N)
    dim3 gQK(CH / 128, HW / 128, BATCH);
    gemm_u<0, 2><<<gQK, 256, SMEM_G>>>(xnT, w,      q, nullptr, bq, HW, CH, CH, 1.f, 0.f, CHW, 0, CHW);
    gemm_u<0, 2><<<gQK, 256, SMEM_G>>>(xnT, w + CC, k, nullptr, bk, HW, CH, CH, 1.f, 0.f, CHW, 0, CHW);

    // 4) V -> fp8 [c, hw]  (bias over M)
    dim3 gV(HW / 128, CH / 128, BATCH);
    gemm_u<0, 2><<<gV, 256, SMEM_G>>>(w + 2 * CC, xnT, v, bv, nullptr, CH, HW, CH, 1.f, 0.f, 0, CHW, CHW);

    // 5) scores f16 (fp8 in, f16 acc)
    const float alpha = 1.0f / sqrtf((float)CH);
    dim3 gS(HW / 128, HW / 128, BATCH);
    gemm_u<1, 1><<<gS, 256, SMEM_G>>>(q, k, s, nullptr, nullptr, HW, HW, CH, alpha, 0.f, CHW, CHW, SHW);

    // 6) softmax -> fp8 attn*256
    softmax_kernel<<<BATCH * HW, 256>>>(s, at);

    // 7) o2[hw, c] = attn @ v^T (fp8 in), alpha undoes the 256 scale
    dim3 gO(CH / 128, HW / 128, BATCH);
    gemm_u<1, 1><<<gO, 256, SMEM_G>>>(at, v, o2, nullptr, nullptr, HW, CH, HW, 1.f / 256.f, 0.f, SHW, CHW, CHW);

    // 8) proj fp32 + bias + 64
    gemm_u<0, 0><<<gV, 256, SMEM_G>>>(w + 3 * CC, o2, out, bp, nullptr, CH, HW, CH, 1.f, 64.0f, 0, CHW, CHW);
}

// round 8
// speedup vs baseline: 1.0127x; 1.0127x over previous
#include <cuda_runtime.h>
#include <cuda_bf16.h>
#include <cuda_fp16.h>
#include <cuda_fp8.h>
#include <cstdint>
#include <math.h>

#define BATCH 4
#define CH    512
#define HW    4096
#define NGRP  32
#define CPG   16

static const size_t CHW  = (size_t)CH * HW;        // 2,097,152
static const size_t QKW  = (size_t)HW * 1024;      // qk batch stride
static const size_t SHW  = (size_t)HW * HW;        // 16,777,216
#define CC (CH * CH)

// ---------------- scratch ----------------
__device__ __nv_bfloat16 g_xn [BATCH * CH * HW];   // [c, hw] bf16
__device__ __nv_bfloat16 g_xnT[BATCH * CH * HW];   // [hw, c] bf16
__device__ uint8_t       g_qk [BATCH * HW * 1024]; // [hw, q(512)|k(512)] fp8
__device__ uint8_t       g_v  [BATCH * CH * HW];   // [c, hw] fp8
__device__ uint8_t       g_s  [BATCH * HW * HW];   // fp8 scores (64 MB)
__device__ uint8_t       g_at [BATCH * HW * HW];   // fp8 attn*256 (64 MB)
__device__ __nv_bfloat16 g_o2 [BATCH * CH * HW];   // [hw, c] bf16
__device__ __nv_bfloat16 g_w  [4 * CH * CH];       // wq, wk, wv, wp bf16
__device__ float         g_bqk[1024];              // concat(bq, bk)

// ---------------- PTX helpers (family-portable) ----------------
__device__ __forceinline__ uint32_t smem_u32(const void* p) {
    uint32_t a;
    asm("{ .reg .u64 t; cvta.to.shared.u64 t, %1; cvt.u32.u64 %0, t; }"
        : "=r"(a) : "l"(p));
    return a;
}
__device__ __forceinline__ void cp16(uint32_t s, const void* g) {
    asm volatile("cp.async.cg.shared.global [%0], [%1], 16;"
                 :: "r"(s), "l"(__cvta_generic_to_global(g)) : "memory");
}
#define CP_COMMIT() asm volatile("cp.async.commit_group;" ::: "memory")
#define CP_WAIT1()  asm volatile("cp.async.wait_group 1;"  ::: "memory")

__device__ __forceinline__ void ldsm_x4(uint32_t* r, uint32_t addr) {
    asm volatile("ldmatrix.sync.aligned.m8n8.x4.shared.b16 {%0,%1,%2,%3}, [%4];"
        : "=r"(r[0]), "=r"(r[1]), "=r"(r[2]), "=r"(r[3]) : "r"(addr));
}
__device__ __forceinline__ void mma16816(float* c, const uint32_t* a,
                                         uint32_t b0, uint32_t b1) {
    asm volatile(
        "mma.sync.aligned.m16n8k16.row.col.f32.bf16.bf16.f32 "
        "{%0,%1,%2,%3}, {%4,%5,%6,%7}, {%8,%9}, {%0,%1,%2,%3};"
        : "+f"(c[0]), "+f"(c[1]), "+f"(c[2]), "+f"(c[3])
        : "r"(a[0]), "r"(a[1]), "r"(a[2]), "r"(a[3]), "r"(b0), "r"(b1));
}
__device__ __forceinline__ void mma_f8h(uint32_t* c, const uint32_t* a,
                                        uint32_t b0, uint32_t b1) {
    asm volatile(
        "mma.sync.aligned.m16n8k32.row.col.f16.e4m3.e4m3.f16 "
        "{%0,%1}, {%2,%3,%4,%5}, {%6,%7}, {%0,%1};"
        : "+r"(c[0]), "+r"(c[1])
        : "r"(a[0]), "r"(a[1]), "r"(a[2]), "r"(a[3]), "r"(b0), "r"(b1));
}
__device__ __forceinline__ uint16_t f2_to_e4m3x2(float x0, float x1) {
    return (uint16_t)__nv_cvt_float2_to_fp8x2(make_float2(x0, x1),
                                              __NV_SATFINITE, __NV_E4M3);
}
__device__ __forceinline__ float2 e4m3x2_to_f2(uint16_t h) {
    __half2_raw hr = __nv_cvt_fp8x2_to_halfraw2((__nv_fp8x2_storage_t)h, __NV_E4M3);
    return __half22float2(*reinterpret_cast<__half2*>(&hr));
}

// ---------------------------------------------------------------------------
// GroupNorm -> bf16 [c, hw]
// ---------------------------------------------------------------------------
__global__ __launch_bounds__(256) void groupnorm_kernel(
    const float* __restrict__ x, const float* __restrict__ scale,
    const float* __restrict__ bias, __nv_bfloat16* __restrict__ xn)
{
    const int b = blockIdx.x / NGRP, g = blockIdx.x % NGRP;
    const size_t base = ((size_t)b * CH + (size_t)g * CPG) * HW;
    const int n4 = CPG * HW / 4;

    const float4* xin = reinterpret_cast<const float4*>(x + base);
    float s = 0.f, ss = 0.f;
    for (int i = threadIdx.x; i < n4; i += 256) {
        float4 t = xin[i];
        s  += t.x + t.y + t.z + t.w;
        ss += t.x * t.x + t.y * t.y + t.z * t.z + t.w * t.w;
    }
    __shared__ float r1[256], r2[256];
    r1[threadIdx.x] = s; r2[threadIdx.x] = ss;
    __syncthreads();
    for (int off = 128; off > 0; off >>= 1) {
        if (threadIdx.x < off) {
            r1[threadIdx.x] += r1[threadIdx.x + off];
            r2[threadIdx.x] += r2[threadIdx.x + off];
        }
        __syncthreads();
    }
    const float inv_n = 1.f / (float)(CPG * HW);
    const float mean = r1[0] * inv_n;
    const float var  = fmaxf(r2[0] * inv_n - mean * mean, 0.f);
    const float rstd = rsqrtf(var + 1e-6f);

    uint2* xo = reinterpret_cast<uint2*>(xn + base);
    for (int i = threadIdx.x; i < n4; i += 256) {
        const int c = g * CPG + (i >> 10);
        const float a = scale[c] * rstd;
        const float d = bias[c] - mean * a;
        float4 t = xin[i];
        __nv_bfloat162 h0 = __floats2bfloat162_rn(t.x * a + d, t.y * a + d);
        __nv_bfloat162 h1 = __floats2bfloat162_rn(t.z * a + d, t.w * a + d);
        uint2 o;
        o.x = *reinterpret_cast<uint32_t*>(&h0);
        o.y = *reinterpret_cast<uint32_t*>(&h1);
        xo[i] = o;
    }
}

// ---------------------------------------------------------------------------
// 16-bit transpose [R, C] -> [C, R]
// ---------------------------------------------------------------------------
__global__ __launch_bounds__(256) void transpose_h16(
    const uint16_t* __restrict__ in, uint16_t* __restrict__ out, int R, int C)
{
    __shared__ uint16_t tile[64][72];
    const size_t zoff = (size_t)blockIdx.z * (size_t)R * C;
    const int r0 = blockIdx.y * 64, c0 = blockIdx.x * 64;

    #pragma unroll
    for (int it = 0; it < 2; it++) {
        int idx = threadIdx.x + it * 256;
        int r = idx >> 3, c8 = idx & 7;
        uint4 v = *reinterpret_cast<const uint4*>(in + zoff + (size_t)(r0 + r) * C + c0 + c8 * 8);
        *reinterpret_cast<uint4*>(&tile[r][c8 * 8]) = v;
    }
    __syncthreads();
    #pragma unroll
    for (int it = 0; it < 2; it++) {
        int idx = threadIdx.x + it * 256;
        int c = idx >> 3, r8 = idx & 7;
        uint16_t tmp[8];
        #pragma unroll
        for (int i = 0; i < 8; i++) tmp[i] = tile[r8 * 8 + i][c];
        *reinterpret_cast<uint4*>(out + zoff + (size_t)(c0 + c) * R + r0 + r8 * 8) =
            *reinterpret_cast<uint4*>(tmp);
    }
}

// ---------------------------------------------------------------------------
// weights fp32 -> bf16 (+ concat bias)
// ---------------------------------------------------------------------------
__global__ __launch_bounds__(256) void cvt_w_kernel(
    const float* __restrict__ a, const float* __restrict__ b,
    const float* __restrict__ c, const float* __restrict__ d,
    const float* __restrict__ bq, const float* __restrict__ bk,
    __nv_bfloat16* __restrict__ w, float* __restrict__ bqk)
{
    const int i = blockIdx.x * 256 + threadIdx.x;
    const float* s = (blockIdx.y == 0) ? a : (blockIdx.y == 1) ? b : (blockIdx.y == 2) ? c : d;
    w[(size_t)blockIdx.y * CC + i] = __float2bfloat16(s[i]);
    if (blockIdx.y == 0 && i < 1024)
        bqk[i] = (i < 512) ? bq[i] : bk[i - 512];
}

// ---------------------------------------------------------------------------
// bf16 GEMM: D[M,N] = alpha*A@B^T + bias_m + bias_n + addc
// A row m at A + m*lda (elements), B row n at B + n*ldb, both K-major.
// OT: 0 = fp32 out, 2 = fp8 out. 128x128 tile, 8 warps 4Mx2N, 3 stages.
// ---------------------------------------------------------------------------
#define PITCH  144
#define OPSZ   18432           // 128 * 144
#define STG_SZ 36864
#define SMEM_TC 110592         // 3 * STG_SZ

template<int OT>
__global__ void __launch_bounds__(256, 2) gemm_tc(
    const __nv_bfloat16* __restrict__ Ag, const __nv_bfloat16* __restrict__ Bg,
    void* __restrict__ Cout,
    const float* __restrict__ bias_m, const float* __restrict__ bias_n,
    int M, int N, int K, int lda, int ldb,
    float alpha, float addc,
    size_t sA, size_t sB, size_t sC)
{
    extern __shared__ __align__(16) char smem[];
    const uint32_t sb = smem_u32(smem);

    const int tid  = threadIdx.x;
    const int lane = tid & 31;
    const int wid  = tid >> 5;
    const int wm   = wid >> 1;
    const int wn   = wid & 1;
    const int bm = blockIdx.y * 128;
    const int bn = blockIdx.x * 128;

    const uint8_t* Ab = (const uint8_t*)(Ag + (size_t)blockIdx.z * sA + (size_t)bm * lda);
    const uint8_t* Bb = (const uint8_t*)(Bg + (size_t)blockIdx.z * sB + (size_t)bn * ldb);

    int rr[4];
    uint32_t so[4], go[4];
    #pragma unroll
    for (int j = 0; j < 4; j++) {
        const int idx = tid + j * 256;
        rr[j] = idx >> 3;
        const int cc = idx & 7;
        so[j] = (uint32_t)rr[j] * PITCH + cc * 16;
        go[j] = cc * 16;
    }

    const int nk = K >> 6;   // 64 bf16 = 128 B per chunk

    #pragma unroll
    for (int s = 0; s < 2; s++) {
        const uint32_t kb = (uint32_t)s * 128;
        const uint32_t st = sb + s * STG_SZ;
        #pragma unroll
        for (int j = 0; j < 4; j++) {
            cp16(st + so[j],        Ab + (size_t)rr[j] * lda * 2 + kb + go[j]);
            cp16(st + OPSZ + so[j], Bb + (size_t)rr[j] * ldb * 2 + kb + go[j]);
        }
        CP_COMMIT();
    }

    float acc[2][8][4];
    #pragma unroll
    for (int i = 0; i < 2; i++)
        #pragma unroll
        for (int j = 0; j < 8; j++)
            #pragma unroll
            for (int t = 0; t < 4; t++) acc[i][j][t] = 0.f;

    const uint32_t lrow = lane & 15;
    const uint32_t lsel = (lane >> 4) * 16;

    int buf = 0;
    for (int ck = 0; ck < nk; ck++) {
        CP_WAIT1();
        __syncthreads();

        if (ck + 2 < nk) {
            const uint32_t kb = (uint32_t)(ck + 2) * 128;
            const uint32_t st = sb + ((buf + 2) % 3) * STG_SZ;
            #pragma unroll
            for (int j = 0; j < 4; j++) {
                cp16(st + so[j],        Ab + (size_t)rr[j] * lda * 2 + kb + go[j]);
                cp16(st + OPSZ + so[j], Bb + (size_t)rr[j] * ldb * 2 + kb + go[j]);
            }
        }
        CP_COMMIT();

        const uint32_t sa  = sb + buf * STG_SZ;
        const uint32_t sbm = sa + OPSZ;
        #pragma unroll
        for (int kf = 0; kf < 4; kf++) {
            const uint32_t kofs = kf * 32 + lsel;
            uint32_t ar[2][4];
            #pragma unroll
            for (int mi = 0; mi < 2; mi++)
                ldsm_x4(ar[mi], sa + (wm * 32 + mi * 16 + lrow) * PITCH + kofs);
            uint32_t br[4][4];
            #pragma unroll
            for (int nb = 0; nb < 4; nb++)
                ldsm_x4(br[nb], sbm + (wn * 64 + nb * 16 + lrow) * PITCH + kofs);
            #pragma unroll
            for (int mi = 0; mi < 2; mi++)
                #pragma unroll
                for (int nj = 0; nj < 8; nj++) {
                    const int nb = nj >> 1, od = nj & 1;
                    mma16816(acc[mi][nj], ar[mi], br[nb][od], br[nb][od + 2]);
                }
        }
        buf = (buf + 1) % 3;
    }

    const int gid = lane >> 2, tig = lane & 3;
    #pragma unroll
    for (int mi = 0; mi < 2; mi++) {
        #pragma unroll
        for (int r2 = 0; r2 < 2; r2++) {
            const int m = bm + wm * 32 + mi * 16 + gid + r2 * 8;
            const float bmv = (bias_m ? bias_m[m] : 0.f) + addc;
            #pragma unroll
            for (int nj = 0; nj < 8; nj++) {
                const int n = bn + wn * 64 + nj * 8 + tig * 2;
                float x0 = acc[mi][nj][r2 * 2]     * alpha + bmv;
                float x1 = acc[mi][nj][r2 * 2 + 1] * alpha + bmv;
                if (bias_n) { x0 += bias_n[n]; x1 += bias_n[n + 1]; }
                const size_t off = (size_t)blockIdx.z * sC + (size_t)m * N + n;
                if (OT == 0) {
                    *reinterpret_cast<float2*>((float*)Cout + off) = make_float2(x0, x1);
                } else {
                    *reinterpret_cast<uint16_t*>((uint8_t*)Cout + off)
                        = f2_to_e4m3x2(x0, x1);
                }
            }
        }
    }
}

// ---------------------------------------------------------------------------
// fp8 attention GEMM, f16 accumulate: D[M,N] = alpha * A[M,K] @ B[N,K]^T
// 128x128 tile, 4 warps (2x2 of 64x64), 128 threads, 128-fp8 K-chunks.
// OT: 1 = bf16 out, 2 = fp8 out.
// ---------------------------------------------------------------------------
template<int OT>
__global__ void __launch_bounds__(128, 2) gemm_f8h(
    const uint8_t* __restrict__ A, const uint8_t* __restrict__ B,
    void* __restrict__ C,
    int M, int N, int K, int lda, int ldb, float alpha,
    size_t sA, size_t sB, size_t sC)
{
    extern __shared__ __align__(16) char smem[];
    const uint32_t sb = smem_u32(smem);

    const int tid  = threadIdx.x;
    const int lane = tid & 31;
    const int wid  = tid >> 5;
    const int wm   = wid >> 1;
    const int wn   = wid & 1;
    const int bm = blockIdx.y * 128;
    const int bn = blockIdx.x * 128;

    const uint8_t* Ab = A + (size_t)blockIdx.z * sA + (size_t)bm * lda;
    const uint8_t* Bb = B + (size_t)blockIdx.z * sB + (size_t)bn * ldb;

    uint32_t so[8], gAo[8], gBo[8];
    #pragma unroll
    for (int j = 0; j < 8; j++) {
        const int idx = tid + j * 128;
        const int row = idx >> 3, cc = idx & 7;
        so[j]  = (uint32_t)row * PITCH + cc * 16;
        gAo[j] = (uint32_t)row * lda + cc * 16;
        gBo[j] = (uint32_t)row * ldb + cc * 16;
    }

    const int nk = K >> 7;

    #pragma unroll
    for (int s = 0; s < 2; s++) {
        const uint32_t kb = (uint32_t)s * 128;
        const uint32_t st = sb + s * STG_SZ;
        #pragma unroll
        for (int j = 0; j < 8; j++) {
            cp16(st + so[j],        Ab + gAo[j] + kb);
            cp16(st + OPSZ + so[j], Bb + gBo[j] + kb);
        }
        CP_COMMIT();
    }

    uint32_t acc[4][8][2];
    #pragma unroll
    for (int i = 0; i < 4; i++)
        #pragma unroll
        for (int j = 0; j < 8; j++) { acc[i][j][0] = 0u; acc[i][j][1] = 0u; }

    const uint32_t lrow = lane & 15;
    const uint32_t lsel = (lane >> 4) * 16;

    int buf = 0;
    for (int ck = 0; ck < nk; ck++) {
        CP_WAIT1();
        __syncthreads();

        if (ck + 2 < nk) {
            const uint32_t kb = (uint32_t)(ck + 2) * 128;
            const uint32_t st = sb + ((buf + 2) % 3) * STG_SZ;
            #pragma unroll
            for (int j = 0; j < 8; j++) {
                cp16(st + so[j],        Ab + gAo[j] + kb);
                cp16(st + OPSZ + so[j], Bb + gBo[j] + kb);
            }
        }
        CP_COMMIT();

        const uint32_t sa  = sb + buf * STG_SZ;
        const uint32_t sbm = sa + OPSZ;
        #pragma unroll
        for (int kf = 0; kf < 4; kf++) {
            const uint32_t kofs = kf * 32 + lsel;
            uint32_t ar[4][4];
            #pragma unroll
            for (int mi = 0; mi < 4; mi++)
                ldsm_x4(ar[mi], sa + (wm * 64 + mi * 16 + lrow) * PITCH + kofs);
            uint32_t br[4][4];
            #pragma unroll
            for (int nb = 0; nb < 4; nb++)
                ldsm_x4(br[nb], sbm + (wn * 64 + nb * 16 + lrow) * PITCH + kofs);
            #pragma unroll
            for (int mi = 0; mi < 4; mi++)
                #pragma unroll
                for (int nj = 0; nj < 8; nj++) {
                    const int nb = nj >> 1, od = nj & 1;
                    mma_f8h(acc[mi][nj], ar[mi], br[nb][od], br[nb][od + 2]);
                }
        }
        buf = (buf + 1) % 3;
    }

    const int gid = lane >> 2, tig = lane & 3;
    #pragma unroll
    for (int mi = 0; mi < 4; mi++) {
        #pragma unroll
        for (int r2 = 0; r2 < 2; r2++) {
            const int m = bm + wm * 64 + mi * 16 + gid + r2 * 8;
            #pragma unroll
            for (int nj = 0; nj < 8; nj++) {
                const int n = bn + wn * 64 + nj * 8 + tig * 2;
                const __half2 h = *reinterpret_cast<const __half2*>(&acc[mi][nj][r2]);
                const float2 f = __half22float2(h);
                const size_t off = (size_t)blockIdx.z * sC + (size_t)m * N + n;
                if (OT == 1) {
                    __nv_bfloat162 ob = __floats2bfloat162_rn(f.x * alpha, f.y * alpha);
                    *reinterpret_cast<uint32_t*>((__nv_bfloat16*)C + off)
                        = *reinterpret_cast<uint32_t*>(&ob);
                } else {
                    *reinterpret_cast<uint16_t*>((uint8_t*)C + off)
                        = f2_to_e4m3x2(f.x * alpha, f.y * alpha);
                }
            }
        }
    }
}

// ---------------------------------------------------------------------------
// Row softmax: fp8 scores in -> fp8 attn*256 out. One block per 4096-row.
// ---------------------------------------------------------------------------
__global__ __launch_bounds__(256) void softmax_kernel(
    const uint8_t* __restrict__ s, uint8_t* __restrict__ at)
{
    const uint4* r4 = reinterpret_cast<const uint4*>(s + (size_t)blockIdx.x * HW);
    uint4* o4 = reinterpret_cast<uint4*>(at + (size_t)blockIdx.x * HW);

    uint4 t = r4[threadIdx.x];
    float v[16];
    {
        const uint32_t* u = reinterpret_cast<const uint32_t*>(&t);
        #pragma unroll
        for (int j = 0; j < 4; j++) {
            float2 f0 = e4m3x2_to_f2((uint16_t)(u[j] & 0xFFFF));
            float2 f1 = e4m3x2_to_f2((uint16_t)(u[j] >> 16));
            v[j * 4 + 0] = f0.x; v[j * 4 + 1] = f0.y;
            v[j * 4 + 2] = f1.x; v[j * 4 + 3] = f1.y;
        }
    }
    float mx = -1e30f;
    #pragma unroll
    for (int i = 0; i < 16; i++) mx = fmaxf(mx, v[i]);

    __shared__ float red[256];
    red[threadIdx.x] = mx;
    __syncthreads();
    for (int off = 128; off > 0; off >>= 1) {
        if (threadIdx.x < off)
            red[threadIdx.x] = fmaxf(red[threadIdx.x], red[threadIdx.x + off]);
        __syncthreads();
    }
    mx = red[0];
    __syncthreads();

    float sum = 0.f;
    #pragma unroll
    for (int i = 0; i < 16; i++) { v[i] = __expf(v[i] - mx); sum += v[i]; }
    red[threadIdx.x] = sum;
    __syncthreads();
    for (int off = 128; off > 0; off >>= 1) {
        if (threadIdx.x < off) red[threadIdx.x] += red[threadIdx.x + off];
        __syncthreads();
    }
    const float inv = 256.f / red[0];

    uint4 o;
    uint32_t* u = reinterpret_cast<uint32_t*>(&o);
    #pragma unroll
    for (int j = 0; j < 4; j++) {
        uint32_t lo = f2_to_e4m3x2(v[j * 4 + 0] * inv, v[j * 4 + 1] * inv);
        uint32_t hi = f2_to_e4m3x2(v[j * 4 + 2] * inv, v[j * 4 + 3] * inv);
        u[j] = lo | (hi << 16);
    }
    o4[threadIdx.x] = o;
}

// ---------------------------------------------------------------------------
// Launch
// ---------------------------------------------------------------------------
extern "C" void kernel_launch(void* const* d_in, const int* in_sizes, int n_in,
                              void* d_out, int out_size)
{
    const float* x  = (const float*)d_in[0];
    const float* gs = (const float*)d_in[1];
    const float* gb = (const float*)d_in[2];
    const float* wq = (const float*)d_in[3];
    const float* bq = (const float*)d_in[4];
    const float* wk = (const float*)d_in[5];
    const float* bk = (const float*)d_in[6];
    const float* wv = (const float*)d_in[7];
    const float* bv = (const float*)d_in[8];
    const float* wp = (const float*)d_in[9];
    const float* bp = (const float*)d_in[10];
    float* out = (float*)d_out;

    __nv_bfloat16 *xn, *xnT, *o2, *w;
    uint8_t *qk, *v, *s, *at;
    float *bqk;
    cudaGetSymbolAddress((void**)&xn,  g_xn);
    cudaGetSymbolAddress((void**)&xnT, g_xnT);
    cudaGetSymbolAddress((void**)&qk,  g_qk);
    cudaGetSymbolAddress((void**)&v,   g_v);
    cudaGetSymbolAddress((void**)&s,   g_s);
    cudaGetSymbolAddress((void**)&at,  g_at);
    cudaGetSymbolAddress((void**)&o2,  g_o2);
    cudaGetSymbolAddress((void**)&w,   g_w);
    cudaGetSymbolAddress((void**)&bqk, g_bqk);

    cudaFuncSetAttribute(gemm_tc<2>,  cudaFuncAttributeMaxDynamicSharedMemorySize, SMEM_TC);
    cudaFuncSetAttribute(gemm_tc<0>,  cudaFuncAttributeMaxDynamicSharedMemorySize, SMEM_TC);
    cudaFuncSetAttribute(gemm_f8h<1>, cudaFuncAttributeMaxDynamicSharedMemorySize, SMEM_TC);
    cudaFuncSetAttribute(gemm_f8h<2>, cudaFuncAttributeMaxDynamicSharedMemorySize, SMEM_TC);

    // 0) weights -> bf16 (wq|wk contiguous) + concat bias
    cvt_w_kernel<<<dim3(CC / 256, 4), 256>>>(wq, wk, wv, wp, bq, bk, w, bqk);

    // 1) GroupNorm -> bf16 [c, hw]
    groupnorm_kernel<<<BATCH * NGRP, 256>>>(x, gs, gb, xn);

    // 2) transpose xn -> xnT [hw, c]
    transpose_h16<<<dim3(HW / 64, CH / 64, BATCH), 256>>>(
        (const uint16_t*)xn, (uint16_t*)xnT, CH, HW);

    // 3) merged QK -> fp8 [hw, 1024]: D = xnT @ [wq;wk]^T + [bq;bk]
    dim3 gQK(1024 / 128, HW / 128, BATCH);   // (8, 32, 4)
    gemm_tc<2><<<gQK, 256, SMEM_TC>>>(xnT, w, qk, nullptr, bqk,
                                      HW, 1024, CH, CH, CH, 1.f, 0.f, CHW, 0, QKW);

    // 4) V -> fp8 [c, hw]
    dim3 gV(HW / 128, CH / 128, BATCH);      // (32, 4, 4)
    gemm_tc<2><<<gV, 256, SMEM_TC>>>(w + 2 * CC, xnT, v, bv, nullptr,
                                     CH, HW, CH, CH, CH, 1.f, 0.f, 0, CHW, CHW);

    // 5) scores -> fp8 (A = qk cols 0..511, B = qk cols 512..1023)
    const float alpha = 1.0f / sqrtf((float)CH);
    dim3 gS(HW / 128, HW / 128, BATCH);      // (32, 32, 4)
    gemm_f8h<2><<<gS, 128, SMEM_TC>>>(qk, qk + 512, s,
                                      HW, HW, CH, 1024, 1024, alpha, QKW, QKW, SHW);

    // 6) softmax fp8 -> fp8 attn*256
    softmax_kernel<<<BATCH * HW, 256>>>(s, at);

    // 7) o2[hw, c] = attn @ v^T, alpha undoes the 256 scale
    dim3 gO(CH / 128, HW / 128, BATCH);      // (4, 32, 4)
    gemm_f8h<1><<<gO, 128, SMEM_TC>>>(at, v, o2,
                                      HW, CH, HW, HW, HW, 1.f / 256.f, SHW, CHW, CHW);

    // 8) proj fp32 + bias + 64
    gemm_tc<0><<<gV, 256, SMEM_TC>>>(w + 3 * CC, o2, out, bp, nullptr,
                                     CH, HW, CH, CH, CH, 1.f, 64.0f, 0, CHW, CHW);
}